// round 17
// baseline (speedup 1.0000x reference)
#include <cuda_runtime.h>
#include <cuda_fp16.h>
#include <cstdint>
#include <math.h>

#define HEAD 64
#define NEMB 1024
#define BATCH 8
#define SEQ   2048
#define MTOT  (BATCH*SEQ)   // 16384
#define NTB   (SEQ/64)      // 32 t-blocks per batch

// scratch: projected k,q,v fp16 (6.3 MB)
// k pre-scaled by log2e/32, v by ln2 (folded softplus constants).
__device__ __half g_kqv[3][MTOT][HEAD];

// D += A*B : m16n8k16 fp16 inputs, fp32 accum
__device__ __forceinline__ void mma16(float c[4], const uint32_t a[4], uint32_t b0, uint32_t b1) {
    asm volatile(
        "mma.sync.aligned.m16n8k16.row.col.f32.f16.f16.f32 "
        "{%0,%1,%2,%3}, {%4,%5,%6,%7}, {%8,%9}, {%0,%1,%2,%3};"
        : "+f"(c[0]), "+f"(c[1]), "+f"(c[2]), "+f"(c[3])
        : "r"(a[0]), "r"(a[1]), "r"(a[2]), "r"(a[3]), "r"(b0), "r"(b1));
}

__device__ __forceinline__ void ldsm4(uint32_t r[4], uint32_t a) {
    asm volatile("ldmatrix.sync.aligned.m8n8.x4.shared.b16 {%0,%1,%2,%3}, [%4];"
        : "=r"(r[0]), "=r"(r[1]), "=r"(r[2]), "=r"(r[3]) : "r"(a));
}
__device__ __forceinline__ void ldsm4t(uint32_t r[4], uint32_t a) {
    asm volatile("ldmatrix.sync.aligned.m8n8.x4.trans.shared.b16 {%0,%1,%2,%3}, [%4];"
        : "=r"(r[0]), "=r"(r[1]), "=r"(r[2]), "=r"(r[3]) : "r"(a));
}

__device__ __forceinline__ uint32_t f2h2(float a, float b) {
    __half2 h = __floats2half2_rn(a, b);
    return *(uint32_t*)&h;
}
__device__ __forceinline__ uint32_t smem32(const void* p) {
    return (uint32_t)__cvta_generic_to_shared(p);
}
__device__ __forceinline__ float ex2f(float x) {
    float y; asm("ex2.approx.ftz.f32 %0, %1;" : "=f"(y) : "f"(x)); return y;
}
__device__ __forceinline__ float lg2f(float x) {
    float y; asm("lg2.approx.ftz.f32 %0, %1;" : "=f"(y) : "f"(x)); return y;
}
// P' = log2(1 + 2^x)  (softplus with scales folded into k and v)
__device__ __forceinline__ float softplus2_f(float x) {
    return lg2f(1.f + ex2f(x));
}

// ---------------------------------------------------------------------------
// Projection via fp16 mma + ldmatrix; W read DIRECTLY (no wt kernel).
// CTA: 128(m) x 192(n), K chunk 32, ping-pong buffers, 1 barrier/chunk.
// x tile: [m][k], row stride 40 halves, A-frags via ldsm4.
// W tile: NATURAL [k][n] layout (32 rows x 192 cols, stride 200 halves);
//         B-frags via ldsm4t (row=k, col=n) — same pattern as attn V path.
// Epilogue folds softplus constants: k *= log2e/32, v *= ln2.
// ---------------------------------------------------------------------------
#define PST 40
#define PSTB 80
#define WST 200
#define WSTB 400
#define PROJ_X_H   (128 * PST)              // halves per x buffer
#define PROJ_W_H   (32 * WST)               // halves per W buffer
#define PROJ_SMEM  ((2 * PROJ_X_H + 2 * PROJ_W_H) * 2)   // 46080 B

__global__ __launch_bounds__(256, 1) void proj_mma_kernel(
    const float* __restrict__ x,
    const float* __restrict__ Wk, const float* __restrict__ Wq, const float* __restrict__ Wv,
    const float* __restrict__ bk, const float* __restrict__ bq, const float* __restrict__ bv)
{
    extern __shared__ __half psm[];
    __half* xsb = psm;                       // 2 x [128][PST]
    __half* wsb = psm + 2 * PROJ_X_H;        // 2 x [32][WST] natural [k][n]

    const int tid  = threadIdx.x;
    const int wid  = tid >> 5, lane = tid & 31;
    const int wm   = wid >> 1, wn = wid & 1;
    const int g    = lane >> 2, t = lane & 3;
    const int m0   = blockIdx.x * 128;
    const int lm   = lane >> 3, lrr = lane & 7;

    const float* __restrict__ Ws[3] = {Wk, Wq, Wv};

    const uint32_t psm32 = smem32(psm);
    const uint32_t xs32[2] = { psm32, psm32 + PROJ_X_H * 2 };
    const uint32_t ws32[2] = { psm32 + 4 * PROJ_X_H, psm32 + 4 * PROJ_X_H + PROJ_W_H * 2 };

    // ldmatrix per-lane offsets (bytes)
    const uint32_t paoff = (uint32_t)((wm * 32 + (lm & 1) * 8 + lrr) * PSTB + (lm >> 1) * 16);
    // trans B: row=k, col=n; warp n-base = wn*96 halves = wn*192 bytes
    const uint32_t pboff = (uint32_t)(((lm & 1) * 8 + lrr) * WSTB + (lm >> 1) * 16 + wn * 192);

    // loader indices
    int xrow[4], xcol[4];
    #pragma unroll
    for (int i = 0; i < 4; ++i) { int idx = i * 256 + tid; xrow[i] = idx >> 3; xcol[i] = (idx & 7) * 4; }
    // W: 6 float4 per thread; idx -> (kk, p, n4)
    int wkk[6], wp[6], wn4[6];
    #pragma unroll
    for (int i = 0; i < 6; ++i) {
        int idx = i * 256 + tid;             // 0..1535
        wkk[i] = idx / 48; int r = idx % 48;
        wp[i] = r >> 4; wn4[i] = (r & 15) * 4;
    }

    float c[2][12][4];
    #pragma unroll
    for (int mt = 0; mt < 2; ++mt)
        #pragma unroll
        for (int nt = 0; nt < 12; ++nt)
            #pragma unroll
            for (int r = 0; r < 4; ++r) c[mt][nt][r] = 0.f;

    uint2 xr[4], wr[6];

    // prologue: chunk 0 -> buffer 0
    #pragma unroll
    for (int i = 0; i < 4; ++i) {
        float4 v = *(const float4*)&x[(size_t)(m0 + xrow[i]) * NEMB + xcol[i]];
        xr[i].x = f2h2(v.x, v.y); xr[i].y = f2h2(v.z, v.w);
    }
    #pragma unroll
    for (int i = 0; i < 6; ++i) {
        float4 v = *(const float4*)&Ws[wp[i]][(size_t)wkk[i] * HEAD + wn4[i]];
        wr[i].x = f2h2(v.x, v.y); wr[i].y = f2h2(v.z, v.w);
    }
    #pragma unroll
    for (int i = 0; i < 4; ++i)
        *(uint2*)&xsb[xrow[i] * PST + xcol[i]] = xr[i];
    #pragma unroll
    for (int i = 0; i < 6; ++i)
        *(uint2*)&wsb[wkk[i] * WST + wp[i] * 64 + wn4[i]] = wr[i];
    __syncthreads();

    for (int ch = 0; ch < 32; ++ch) {
        const int cur = ch & 1;
        __half* xsn = xsb + (cur ^ 1) * PROJ_X_H;
        __half* wsn = wsb + (cur ^ 1) * PROJ_W_H;

        // prefetch next chunk into registers
        if (ch < 31) {
            const int k1 = (ch + 1) * 32;
            #pragma unroll
            for (int i = 0; i < 4; ++i) {
                float4 v = *(const float4*)&x[(size_t)(m0 + xrow[i]) * NEMB + k1 + xcol[i]];
                xr[i].x = f2h2(v.x, v.y); xr[i].y = f2h2(v.z, v.w);
            }
            #pragma unroll
            for (int i = 0; i < 6; ++i) {
                float4 v = *(const float4*)&Ws[wp[i]][(size_t)(k1 + wkk[i]) * HEAD + wn4[i]];
                wr[i].x = f2h2(v.x, v.y); wr[i].y = f2h2(v.z, v.w);
            }
        }

        // A fragments via ldsm4
        uint32_t A[2][2][4];
        #pragma unroll
        for (int mt = 0; mt < 2; ++mt)
            #pragma unroll
            for (int kt = 0; kt < 2; ++kt)
                ldsm4(A[mt][kt], xs32[cur] + paoff + (uint32_t)(mt * 16 * PSTB + kt * 32));

        // B fragments via ldsm4t from natural [k][n] tile
        #pragma unroll
        for (int kt = 0; kt < 2; ++kt) {
            #pragma unroll
            for (int p2 = 0; p2 < 6; ++p2) {
                uint32_t B4[4];
                ldsm4t(B4, ws32[cur] + pboff + (uint32_t)(kt * 16 * WSTB + p2 * 32));
                mma16(c[0][2 * p2    ], A[0][kt], B4[0], B4[1]);
                mma16(c[0][2 * p2 + 1], A[0][kt], B4[2], B4[3]);
                mma16(c[1][2 * p2    ], A[1][kt], B4[0], B4[1]);
                mma16(c[1][2 * p2 + 1], A[1][kt], B4[2], B4[3]);
            }
        }

        if (ch < 31) {
            #pragma unroll
            for (int i = 0; i < 4; ++i)
                *(uint2*)&xsn[xrow[i] * PST + xcol[i]] = xr[i];
            #pragma unroll
            for (int i = 0; i < 6; ++i)
                *(uint2*)&wsn[wkk[i] * WST + wp[i] * 64 + wn4[i]] = wr[i];
        }
        __syncthreads();
    }

    // epilogue: fp32 bias add, constant fold, fp16 store
    const float* biases[3] = {bk, bq, bv};
    const float scales[3] = {0.04511294f, 1.f, 0.69314718f};  // log2e/32, 1, ln2
    #pragma unroll
    for (int nt = 0; nt < 12; ++nt) {
        const int ng0 = wn * 96 + nt * 8;
        const int p = ng0 >> 6;
        const int n = (ng0 & 63) + 2 * t;
        const float* __restrict__ bias = biases[p];
        const float sc = scales[p];
        const float b0 = bias[n], b1 = bias[n + 1];
        #pragma unroll
        for (int mt = 0; mt < 2; ++mt) {
            const int row = m0 + wm * 32 + mt * 16 + g;
            *(uint32_t*)&g_kqv[p][row    ][n] = f2h2((c[mt][nt][0] + b0) * sc, (c[mt][nt][1] + b1) * sc);
            *(uint32_t*)&g_kqv[p][row + 8][n] = f2h2((c[mt][nt][2] + b0) * sc, (c[mt][nt][3] + b1) * sc);
        }
    }
}

// ---------------------------------------------------------------------------
// Attention: rolling phase pipeline. Per iteration:
//   S-mma(sb+1) -> softplus(sb) [MUFU overlaps tensor] -> O-mma(sb)
//   -> store prefetched (sb+2) -> one barrier.
// Two s_c accumulator banks; 4 Q/V smem slots; P in registers; f32 accum.
// ---------------------------------------------------------------------------
#define ASTH 72
#define ASTB 144
#define TILE_H (64 * ASTH)
#define ATTN_SMEM (9 * TILE_H * 2)          // ks + 4*qs + 4*vs = 82944 B

__global__ __launch_bounds__(256, 1) void attn_kernel(float* __restrict__ out)
{
    extern __shared__ __half smh[];
    __half* ks  = smh;                       // [64][ASTH]  K tile [t][h]
    __half* qsb = smh + TILE_H;              // 4 x Q tiles [s][h]
    __half* vsb = smh + 5 * TILE_H;          // 4 x V tiles [s][h] (natural)
    float*  stage = (float*)qsb;             // epilogue staging (reused)

    const int b    = blockIdx.y;
    const int tid  = threadIdx.x;
    const int wid  = tid >> 5, lane = tid & 31;
    const int wm   = wid >> 1, wn = wid & 1;
    const int g    = lane >> 2, t = lane & 3;
    const int lm   = lane >> 3, lrr = lane & 7;
    const int trow = wm * 16 + g;

    const uint32_t sm32 = smem32(smh);
    const uint32_t ks32 = sm32;
    uint32_t qs32[4], vs32[4];
    #pragma unroll
    for (int s = 0; s < 4; ++s) {
        qs32[s] = sm32 + (uint32_t)((1 + s) * TILE_H * 2);
        vs32[s] = sm32 + (uint32_t)((5 + s) * TILE_H * 2);
    }

    const uint32_t kaoff = (uint32_t)((wm * 16 + (lm & 1) * 8 + lrr) * ASTB + (lm >> 1) * 16);
    const uint32_t qboff = (uint32_t)((wn * 32 + (lm >> 1) * 8 + lrr) * ASTB + (lm & 1) * 16);
    const uint32_t vboff = (uint32_t)(((lm & 1) * 8 + lrr) * ASTB + (lm >> 1) * 16);

    int qrow[4], qcol[4];
    #pragma unroll
    for (int i = 0; i < 4; ++i) { int idx = i * 256 + tid; qrow[i] = idx >> 4; qcol[i] = (idx & 15) * 4; }

    const __half* __restrict__ Kg = &g_kqv[0][(size_t)b * SEQ][0];
    const __half* __restrict__ Qg = &g_kqv[1][(size_t)b * SEQ][0];
    const __half* __restrict__ Vg = &g_kqv[2][(size_t)b * SEQ][0];

    for (int hf = 0; hf < 2; ++hf) {
        const int tb = hf ? (NTB - 1 - (int)blockIdx.x) : (int)blockIdx.x;

        // K tile [t][h]
        #pragma unroll
        for (int i = 0; i < 4; ++i) {
            uint2 u = *(const uint2*)&Kg[(size_t)(tb * 64 + qrow[i]) * HEAD + qcol[i]];
            *(uint2*)&ks[qrow[i] * ASTH + qcol[i]] = u;
        }

        // prologue: slots 0 (and 1 if tb>=1)
        #pragma unroll
        for (int blk = 0; blk < 2; ++blk) {
            if (blk > tb) break;
            __half* qs = qsb + blk * TILE_H;
            __half* vs = vsb + blk * TILE_H;
            const size_t s0 = (size_t)blk * 64;
            #pragma unroll
            for (int i = 0; i < 4; ++i) {
                *(uint2*)&qs[qrow[i] * ASTH + qcol[i]] =
                    *(const uint2*)&Qg[(s0 + qrow[i]) * HEAD + qcol[i]];
                *(uint2*)&vs[qrow[i] * ASTH + qcol[i]] =
                    *(const uint2*)&Vg[(s0 + qrow[i]) * HEAD + qcol[i]];
            }
        }
        __syncthreads();

        // K A-fragments, resident across the s-loop
        uint32_t A[4][4];
        #pragma unroll
        for (int kt = 0; kt < 4; ++kt)
            ldsm4(A[kt], ks32 + kaoff + (uint32_t)(kt * 32));

        float o[8][4];
        #pragma unroll
        for (int nt = 0; nt < 8; ++nt)
            #pragma unroll
            for (int r = 0; r < 4; ++r) o[nt][r] = 0.f;

        // two s_c banks; compute S(0) into bank 0
        float s_c[2][4][4];
        #pragma unroll
        for (int nt = 0; nt < 4; ++nt)
            #pragma unroll
            for (int r = 0; r < 4; ++r) s_c[0][nt][r] = 0.f;
        #pragma unroll
        for (int kt = 0; kt < 4; ++kt) {
            #pragma unroll
            for (int p2 = 0; p2 < 2; ++p2) {
                uint32_t B4[4];
                ldsm4(B4, qs32[0] + qboff + (uint32_t)(p2 * 16 * ASTB + kt * 32));
                mma16(s_c[0][2 * p2    ], A[kt], B4[0], B4[1]);
                mma16(s_c[0][2 * p2 + 1], A[kt], B4[2], B4[3]);
            }
        }

        uint2 qrh[4], vrh[4];

        for (int sb = 0; sb <= tb; ++sb) {
            const int cur = sb & 1;

            // prefetch sb+2
            const int pf = sb + 2;
            const bool vf = pf <= tb;
            if (vf) {
                const size_t s1 = (size_t)pf * 64;
                #pragma unroll
                for (int i = 0; i < 4; ++i) {
                    qrh[i] = *(const uint2*)&Qg[(s1 + qrow[i]) * HEAD + qcol[i]];
                    vrh[i] = *(const uint2*)&Vg[(s1 + qrow[i]) * HEAD + qcol[i]];
                }
            }

            // S-mma(sb+1) into the other bank (tensor pipe; softplus below
            // depends only on bank cur, so MUFU overlaps this)
            if (sb < tb) {
                #pragma unroll
                for (int nt = 0; nt < 4; ++nt)
                    #pragma unroll
                    for (int r = 0; r < 4; ++r) s_c[cur ^ 1][nt][r] = 0.f;
                const uint32_t qb = qs32[(sb + 1) & 3];
                #pragma unroll
                for (int kt = 0; kt < 4; ++kt) {
                    #pragma unroll
                    for (int p2 = 0; p2 < 2; ++p2) {
                        uint32_t B4[4];
                        ldsm4(B4, qb + qboff + (uint32_t)(p2 * 16 * ASTB + kt * 32));
                        mma16(s_c[cur ^ 1][2 * p2    ], A[kt], B4[0], B4[1]);
                        mma16(s_c[cur ^ 1][2 * p2 + 1], A[kt], B4[2], B4[3]);
                    }
                }
            }

            // softplus(sb) from bank cur -> pa (registers)
            const bool diag = (sb == tb);
            uint32_t pa[2][4];
            #pragma unroll
            for (int nt = 0; nt < 4; ++nt) {
                const int sc = wn * 32 + nt * 8 + 2 * t;
                float p0 = softplus2_f(s_c[cur][nt][0]);
                float p1 = softplus2_f(s_c[cur][nt][1]);
                float p2 = softplus2_f(s_c[cur][nt][2]);
                float p3 = softplus2_f(s_c[cur][nt][3]);
                if (diag) {
                    if (sc     > trow    ) p0 = 0.f;
                    if (sc + 1 > trow    ) p1 = 0.f;
                    if (sc     > trow + 8) p2 = 0.f;
                    if (sc + 1 > trow + 8) p3 = 0.f;
                }
                const int j = nt >> 1;
                if ((nt & 1) == 0) { pa[j][0] = f2h2(p0, p1); pa[j][1] = f2h2(p2, p3); }
                else               { pa[j][2] = f2h2(p0, p1); pa[j][3] = f2h2(p2, p3); }
            }

            // O-mma(sb) (B via ldmatrix.trans from natural V)
            {
                const uint32_t vb = vs32[sb & 3];
                #pragma unroll
                for (int j = 0; j < 2; ++j) {
                    const uint32_t vjb = vb + (uint32_t)((wn * 32 + j * 16) * ASTB) + vboff;
                    #pragma unroll
                    for (int q = 0; q < 4; ++q) {
                        uint32_t B4[4];
                        ldsm4t(B4, vjb + (uint32_t)(q * 32));
                        mma16(o[2 * q    ], pa[j], B4[0], B4[1]);
                        mma16(o[2 * q + 1], pa[j], B4[2], B4[3]);
                    }
                }
            }

            // store prefetched (sb+2) into slot (sb+2)%4 (its readers finished
            // >=2 barriers ago), then one barrier
            if (vf) {
                __half* qsn = qsb + (pf & 3) * TILE_H;
                __half* vsn = vsb + (pf & 3) * TILE_H;
                #pragma unroll
                for (int i = 0; i < 4; ++i) {
                    *(uint2*)&qsn[qrow[i] * ASTH + qcol[i]] = qrh[i];
                    *(uint2*)&vsn[qrow[i] * ASTH + qcol[i]] = vrh[i];
                }
            }
            __syncthreads();
        }

        // cross-wn reduction (once per t-block): wn=1 stages, wn=0 adds+writes
        if (wn == 1) {
            #pragma unroll
            for (int nt = 0; nt < 8; ++nt) {
                const int col = nt * 8 + 2 * t;
                *(float2*)&stage[(wm * 16 + g    ) * 64 + col] = make_float2(o[nt][0], o[nt][1]);
                *(float2*)&stage[(wm * 16 + g + 8) * 64 + col] = make_float2(o[nt][2], o[nt][3]);
            }
        }
        __syncthreads();
        if (wn == 0) {
            const size_t row0 = (size_t)b * SEQ + tb * 64 + trow;
            #pragma unroll
            for (int nt = 0; nt < 8; ++nt) {
                const int col = nt * 8 + 2 * t;
                float2 s0 = *(const float2*)&stage[(wm * 16 + g    ) * 64 + col];
                float2 s1 = *(const float2*)&stage[(wm * 16 + g + 8) * 64 + col];
                *(float2*)&out[(row0    ) * HEAD + col] = make_float2(o[nt][0] + s0.x, o[nt][1] + s0.y);
                *(float2*)&out[(row0 + 8) * HEAD + col] = make_float2(o[nt][2] + s1.x, o[nt][3] + s1.y);
            }
        }
        __syncthreads();
    }
}

// ---------------------------------------------------------------------------
extern "C" void kernel_launch(void* const* d_in, const int* in_sizes, int n_in,
                              void* d_out, int out_size)
{
    const float* x  = (const float*)d_in[0];
    const float* Wk = (const float*)d_in[1];
    const float* bk = (const float*)d_in[2];
    const float* Wq = (const float*)d_in[3];
    const float* bq = (const float*)d_in[4];
    const float* Wv = (const float*)d_in[5];
    const float* bv = (const float*)d_in[6];
    float* out = (float*)d_out;

    static int init = 0;
    if (!init) {
        cudaFuncSetAttribute(attn_kernel, cudaFuncAttributeMaxDynamicSharedMemorySize, ATTN_SMEM);
        cudaFuncSetAttribute(proj_mma_kernel, cudaFuncAttributeMaxDynamicSharedMemorySize, PROJ_SMEM);
        init = 1;
    }

    proj_mma_kernel<<<MTOT / 128, 256, PROJ_SMEM>>>(x, Wk, Wq, Wv, bk, bq, bv);

    dim3 ag(NTB / 2, BATCH);
    attn_kernel<<<ag, 256, ATTN_SMEM>>>(out);
}